// round 2
// baseline (speedup 1.0000x reference)
#include <cuda_runtime.h>

// Problem constants (capacities for static scratch; runtime sizes used in loops)
#define NNODES 150000
#define MAXE   2000000
#define EMB4   32          // 128 floats = 32 float4 per node row
#define SCANB  1024        // scan block size
#define MAXB   16384       // batch capacity
#define MAXROWS (2*MAXB)   // max unique sampled rows

// ---------------- static device scratch (sanctioned workaround) -------------
__device__ float4 g_h1[NNODES * EMB4];   // layer 1
__device__ float4 g_h2[NNODES * EMB4];   // layer 2
__device__ float4 g_h3[NNODES * EMB4];   // layer 3 (written only at needed rows)
__device__ int    g_cnt[NNODES];         // per-row degree histogram
__device__ int    g_rowptr[NNODES + 1];  // CSR row pointers
__device__ int    g_cursor[NNODES];      // counting-sort cursors
__device__ int2   g_edge[MAXE];          // CSR {col, val-bits}
__device__ int    g_partials[512];       // scan block partials
__device__ unsigned char g_need[NNODES]; // sampled-row flags
__device__ int    g_rows[MAXROWS];       // compacted needed rows
__device__ int    g_nrows;               // count of needed rows

// ---------------- CSR build ------------------------------------------------

__global__ void k_zero(int n) {
    int i = blockIdx.x * blockDim.x + threadIdx.x;
    if (i < n) { g_cnt[i] = 0; g_need[i] = 0; }
    if (i == 0) g_nrows = 0;
}

__global__ void k_hist(const int* __restrict__ row, int e) {
    int i = blockIdx.x * blockDim.x + threadIdx.x;
    if (i < e) atomicAdd(&g_cnt[row[i]], 1);
}

// per-block sums of g_cnt into g_partials
__global__ void k_block_sums(int n) {
    __shared__ int sh[SCANB];
    int gid = blockIdx.x * SCANB + threadIdx.x;
    sh[threadIdx.x] = (gid < n) ? g_cnt[gid] : 0;
    __syncthreads();
    for (int off = SCANB / 2; off > 0; off >>= 1) {
        if (threadIdx.x < off) sh[threadIdx.x] += sh[threadIdx.x + off];
        __syncthreads();
    }
    if (threadIdx.x == 0) g_partials[blockIdx.x] = sh[0];
}

// parallel exclusive scan of block partials (nb <= 256); g_rowptr[n] = total
__global__ void k_scan_partials(int nb, int n) {
    __shared__ int sh[256];
    int v = (threadIdx.x < nb) ? g_partials[threadIdx.x] : 0;
    sh[threadIdx.x] = v;
    __syncthreads();
    // Hillis-Steele inclusive scan over 256
    for (int off = 1; off < 256; off <<= 1) {
        int t = (threadIdx.x >= off) ? sh[threadIdx.x - off] : 0;
        __syncthreads();
        sh[threadIdx.x] += t;
        __syncthreads();
    }
    if (threadIdx.x < nb) g_partials[threadIdx.x] = sh[threadIdx.x] - v;  // exclusive
    if (threadIdx.x == 255) g_rowptr[n] = sh[255];
}

// per-block exclusive scan + partial offset -> g_rowptr, g_cursor
__global__ void k_scan_final(int n) {
    __shared__ int sh[SCANB];
    int gid = blockIdx.x * SCANB + threadIdx.x;
    int v = (gid < n) ? g_cnt[gid] : 0;
    sh[threadIdx.x] = v;
    __syncthreads();
    for (int off = 1; off < SCANB; off <<= 1) {
        int t = (threadIdx.x >= off) ? sh[threadIdx.x - off] : 0;
        __syncthreads();
        sh[threadIdx.x] += t;
        __syncthreads();
    }
    if (gid < n) {
        int excl = sh[threadIdx.x] - v + g_partials[blockIdx.x];
        g_rowptr[gid] = excl;
        g_cursor[gid] = excl;
    }
}

// counting-sort edges into CSR slots (fused col+val -> one 8B store)
__global__ void k_fill(const int* __restrict__ row, const int* __restrict__ col,
                       const float* __restrict__ val, int e) {
    int i = blockIdx.x * blockDim.x + threadIdx.x;
    if (i < e) {
        int r = row[i];
        int p = atomicAdd(&g_cursor[r], 1);
        g_edge[p] = make_int2(col[i], __float_as_int(val[i]));
    }
}

// ---------------- needed-row marking / compaction ---------------------------

__global__ void k_mark(const int* __restrict__ uIdx, const int* __restrict__ vIdx,
                       int userNum, int B) {
    int i = blockIdx.x * blockDim.x + threadIdx.x;
    if (i < B) {
        g_need[uIdx[i]] = 1;
        g_need[vIdx[i] + userNum] = 1;
    }
}

__global__ void k_compact(int n) {
    int i = blockIdx.x * blockDim.x + threadIdx.x;
    int lane = threadIdx.x & 31;
    int flag = (i < n) ? (int)g_need[i] : 0;
    unsigned m = __ballot_sync(0xffffffffu, flag);
    int cnt = __popc(m);
    if (cnt == 0) return;
    int base = 0;
    if (lane == 0) base = atomicAdd(&g_nrows, cnt);
    base = __shfl_sync(0xffffffffu, base, 0);
    if (flag) g_rows[base + __popc(m & ((1u << lane) - 1u))] = i;
}

// ---------------- SpMM ------------------------------------------------------

// Shared warp-level row gather: acc = sum_e val * hin(col)
// hin is selected per column by the caller-provided lambda-ish macro pattern;
// we instead specialize three kernels to keep SASS simple.

// layer 1: gather directly from uE/iE (no h0 materialization)
__global__ void k_spmm1(const float4* __restrict__ uE, const float4* __restrict__ iE,
                        int userNum, int n) {
    int w    = (blockIdx.x * blockDim.x + threadIdx.x) >> 5;
    int lane = threadIdx.x & 31;
    if (w >= n) return;
    int s = g_rowptr[w];
    int e = g_rowptr[w + 1];
    float4 acc = make_float4(0.f, 0.f, 0.f, 0.f);
    for (int base = s; base < e; base += 32) {
        int idx = base + lane;
        int2 ed = (idx < e) ? g_edge[idx] : make_int2(0, 0);
        int m = min(32, e - base);
        #pragma unroll 4
        for (int j = 0; j < m; j++) {
            int   cj = __shfl_sync(0xffffffffu, ed.x, j);
            float vj = __shfl_sync(0xffffffffu, __int_as_float(ed.y), j);
            const float4* src = (cj < userNum) ? (uE + (size_t)cj * EMB4)
                                               : (iE + (size_t)(cj - userNum) * EMB4);
            float4 x = src[lane];
            acc.x = fmaf(vj, x.x, acc.x);
            acc.y = fmaf(vj, x.y, acc.y);
            acc.z = fmaf(vj, x.z, acc.z);
            acc.w = fmaf(vj, x.w, acc.w);
        }
    }
    g_h1[w * EMB4 + lane] = acc;
}

// layer 2: g_h1 -> g_h2, all rows
__global__ void k_spmm2(int n) {
    int w    = (blockIdx.x * blockDim.x + threadIdx.x) >> 5;
    int lane = threadIdx.x & 31;
    if (w >= n) return;
    int s = g_rowptr[w];
    int e = g_rowptr[w + 1];
    float4 acc = make_float4(0.f, 0.f, 0.f, 0.f);
    for (int base = s; base < e; base += 32) {
        int idx = base + lane;
        int2 ed = (idx < e) ? g_edge[idx] : make_int2(0, 0);
        int m = min(32, e - base);
        #pragma unroll 4
        for (int j = 0; j < m; j++) {
            int   cj = __shfl_sync(0xffffffffu, ed.x, j);
            float vj = __shfl_sync(0xffffffffu, __int_as_float(ed.y), j);
            float4 x = g_h1[(size_t)cj * EMB4 + lane];
            acc.x = fmaf(vj, x.x, acc.x);
            acc.y = fmaf(vj, x.y, acc.y);
            acc.z = fmaf(vj, x.z, acc.z);
            acc.w = fmaf(vj, x.w, acc.w);
        }
    }
    g_h2[w * EMB4 + lane] = acc;
}

// layer 3: g_h2 -> g_h3, restricted to compacted needed rows
__global__ void k_spmm3() {
    int w    = (blockIdx.x * blockDim.x + threadIdx.x) >> 5;
    int lane = threadIdx.x & 31;
    if (w >= g_nrows) return;
    int r = g_rows[w];
    int s = g_rowptr[r];
    int e = g_rowptr[r + 1];
    float4 acc = make_float4(0.f, 0.f, 0.f, 0.f);
    for (int base = s; base < e; base += 32) {
        int idx = base + lane;
        int2 ed = (idx < e) ? g_edge[idx] : make_int2(0, 0);
        int m = min(32, e - base);
        #pragma unroll 4
        for (int j = 0; j < m; j++) {
            int   cj = __shfl_sync(0xffffffffu, ed.x, j);
            float vj = __shfl_sync(0xffffffffu, __int_as_float(ed.y), j);
            float4 x = g_h2[(size_t)cj * EMB4 + lane];
            acc.x = fmaf(vj, x.x, acc.x);
            acc.y = fmaf(vj, x.y, acc.y);
            acc.z = fmaf(vj, x.z, acc.z);
            acc.w = fmaf(vj, x.w, acc.w);
        }
    }
    g_h3[r * EMB4 + lane] = acc;
}

// ---------------- final dot --------------------------------------------------

__global__ void k_dot(const float4* __restrict__ uE, const float4* __restrict__ iE,
                      const int* __restrict__ uIdx, const int* __restrict__ vIdx,
                      int userNum, int B, float* __restrict__ out) {
    int w    = (blockIdx.x * blockDim.x + threadIdx.x) >> 5;
    int lane = threadIdx.x & 31;
    if (w >= B) return;

    int u  = uIdx[w];
    int vi = vIdx[w];
    int v  = vi + userNum;
    size_t ub = (size_t)u * EMB4 + lane;
    size_t vb = (size_t)v * EMB4 + lane;

    float4 a0 = uE[(size_t)u * EMB4 + lane];
    float4 b0 = iE[(size_t)vi * EMB4 + lane];
    float4 a1 = g_h1[ub], a2 = g_h2[ub], a3 = g_h3[ub];
    float4 b1 = g_h1[vb], b2 = g_h2[vb], b3 = g_h3[vb];

    float sux = a0.x + a1.x + a2.x + a3.x, svx = b0.x + b1.x + b2.x + b3.x;
    float suy = a0.y + a1.y + a2.y + a3.y, svy = b0.y + b1.y + b2.y + b3.y;
    float suz = a0.z + a1.z + a2.z + a3.z, svz = b0.z + b1.z + b2.z + b3.z;
    float suw = a0.w + a1.w + a2.w + a3.w, svw = b0.w + b1.w + b2.w + b3.w;

    float d = sux * svx + suy * svy + suz * svz + suw * svw;
    #pragma unroll
    for (int off = 16; off > 0; off >>= 1)
        d += __shfl_xor_sync(0xffffffffu, d, off);

    if (lane == 0) out[w] = d * 0.0625f;   // (1/4)*(1/4) layer average
}

// ---------------- launch ----------------------------------------------------

extern "C" void kernel_launch(void* const* d_in, const int* in_sizes, int n_in,
                              void* d_out, int out_size) {
    const float4* uE   = (const float4*)d_in[0];
    const float4* iE   = (const float4*)d_in[1];
    const float*  Lval = (const float*)d_in[2];
    const int*    Lrow = (const int*)d_in[3];
    const int*    Lcol = (const int*)d_in[4];
    const int*    uIdx = (const int*)d_in[5];
    const int*    vIdx = (const int*)d_in[6];
    float*        out  = (float*)d_out;

    int userNum = in_sizes[0] / 128;
    int itemNum = in_sizes[1] / 128;
    int n = userNum + itemNum;
    if (n > NNODES) n = NNODES;
    int e = in_sizes[2];
    if (e > MAXE) e = MAXE;
    int B = in_sizes[5];
    if (B > MAXB) B = MAXB;

    // CSR build + needed-row marking
    k_zero<<<(n + 255) / 256, 256>>>(n);
    k_hist<<<(e + 255) / 256, 256>>>(Lrow, e);
    int nb = (n + SCANB - 1) / SCANB;
    k_block_sums<<<nb, SCANB>>>(n);
    k_scan_partials<<<1, 256>>>(nb, n);
    k_scan_final<<<nb, SCANB>>>(n);
    k_fill<<<(e + 255) / 256, 256>>>(Lrow, Lcol, Lval, e);
    k_mark<<<(B + 255) / 256, 256>>>(uIdx, vIdx, userNum, B);
    k_compact<<<(n + 255) / 256, 256>>>(n);

    // 3 SpMM layers (warp per row, 8 warps/block)
    int spmm_blocks = (n + 7) / 8;
    k_spmm1<<<spmm_blocks, 256>>>(uE, iE, userNum, n);
    k_spmm2<<<spmm_blocks, 256>>>(n);
    k_spmm3<<<(MAXROWS + 7) / 8, 256>>>();   // early-exits past g_nrows

    // final batched dot
    k_dot<<<(B + 7) / 8, 256>>>(uE, iE, uIdx, vIdx, userNum, B, out);
}